// round 14
// baseline (speedup 1.0000x reference)
#include <cuda_runtime.h>
#include <math.h>
#include <stdint.h>

#define Kk 256
#define Tt 512
#define NBb 256
#define Vv 4096

#define NT 256
#define NC (NBb/2)      // 128 CTAs, 2 sequences each

// Warp tiling: 8 warps = 2 (p) x 4 (q). Warp (p,q): output states
// {128p+32m+lane, m=0..3}, summation i in [64q,64q+64).
// Per thread: 4 states x 64 i = 128 u64 pairs; 88 in regs (c=0..21 per state),
// 40 via smem (c=22..31). Two barriers per step (champion R7 structure),
// slice-sum accumulated inside the dot, partials exchanged as packed u64
// (both sequences in one STS.64/LDS.64).

typedef unsigned long long ull;

// ---------------- device scratch ----------------
__device__ ull  g_Freg[88*NT];     // forward  A-pack, register part
__device__ ull  g_Fsm [40*NT];     // forward  A-pack, smem part
__device__ ull  g_Breg[88*NT];     // backward A-pack, register part
__device__ ull  g_Bsm [40*NT];     // backward A-pack, smem part
__device__ float g_Bt[Vv*Kk];      // exp(log_B) transposed: [v][j]
__device__ float g_pi[Kk];

// ---------------- prep ----------------
__global__ void prep_pack(const float* __restrict__ logA, const float* __restrict__ logpi) {
    int idx = blockIdx.x * blockDim.x + threadIdx.x;   // 0 .. 32767
    if (idx < Kk) g_pi[idx] = expf(logpi[idx]);
    int tid = idx & 255;
    int k   = idx >> 8;            // 0..127 : k = m*32 + c
    int m = k >> 5, c = k & 31;
    int wi = tid >> 5, l = tid & 31;
    int p = wi >> 2, q = wi & 3;
    int j = 128*p + 32*m + l;      // output state
    int i = 64*q + 2*c;            // summation index (pair base)
    float f0 = expf(logA[i*Kk + j]);        // fwd: sum_i e[i]*A[i][j]
    float f1 = expf(logA[(i+1)*Kk + j]);
    float b0 = expf(logA[j*Kk + i]);        // bwd: sum_i e[i]*A[j][i]
    float b1 = expf(logA[j*Kk + i + 1]);
    ull fv = ((ull)__float_as_uint(f1) << 32) | __float_as_uint(f0);
    ull bv = ((ull)__float_as_uint(b1) << 32) | __float_as_uint(b0);
    if (c < 22) {
        g_Freg[(m*22 + c)*NT + tid] = fv;
        g_Breg[(m*22 + c)*NT + tid] = bv;
    } else {
        int cc = c - 22;           // 0..9
        int u = (((m*5 + (cc>>1))*NT + tid) << 1) | (cc & 1);  // ulonglong2-friendly
        g_Fsm[u] = fv;
        g_Bsm[u] = bv;
    }
}

__global__ void prep_B(const float* __restrict__ logB) {
    int idx = blockIdx.x * blockDim.x + threadIdx.x;   // j*Vv + v (coalesced read)
    if (idx >= Kk*Vv) return;
    int j = idx / Vv, v = idx % Vv;
    g_Bt[v*Kk + j] = expf(logB[idx]);
}

// ---------------- helpers ----------------
__device__ __forceinline__ void ffma2(ull& d, ull a, ull b) {
    asm("fma.rn.f32x2 %0, %1, %2, %0;" : "+l"(d) : "l"(a), "l"(b));
}
__device__ __forceinline__ void fadd2(ull& d, ull a) {
    asm("add.rn.f32x2 %0, %0, %1;" : "+l"(d) : "l"(a));
}
__device__ __forceinline__ float psum1(ull a) {
    unsigned lo, hi; asm("mov.b64 {%0,%1}, %2;" : "=r"(lo), "=r"(hi) : "l"(a));
    return __uint_as_float(lo) + __uint_as_float(hi);
}
__device__ __forceinline__ ull packf2(float lo, float hi) {
    ull r; asm("mov.b64 %0, {%1,%2};" : "=l"(r) : "r"(__float_as_uint(lo)), "r"(__float_as_uint(hi)));
    return r;
}
__device__ __forceinline__ void unpackf2(ull a, float& lo, float& hi) {
    unsigned ulo, uhi; asm("mov.b64 {%0,%1}, %2;" : "=r"(ulo), "=r"(uhi) : "l"(a));
    lo = __uint_as_float(ulo); hi = __uint_as_float(uhi);
}

// split-K dot: warp covers i in [64q,64q+64) for its 4 states x 2 seqs.
// Writes packed partials (seq0 lo, seq1 hi) and its slice-sum of seq p.
__device__ __forceinline__ void do_dot(const ull (&ra)[88],
                                       const ull* __restrict__ As2,
                                       const float* __restrict__ es,   // [2][Kk]
                                       ull* __restrict__ part,         // [4q][256j] packed
                                       float* __restrict__ ssum,       // [2][4]
                                       int p, int q, int l, int tid) {
    const ulonglong2* e0 = reinterpret_cast<const ulonglong2*>(es + 64*q);
    const ulonglong2* e1 = reinterpret_cast<const ulonglong2*>(es + Kk + 64*q);
    ull acc[4][2] = {};
    ull cs = 0;
    // register half: e pairs 0..21 (ulonglong2 0..10)
    #pragma unroll
    for (int h = 0; h < 11; h++) {
        ulonglong2 v0 = e0[h], v1 = e1[h];
        if (p == 0) { fadd2(cs, v0.x); fadd2(cs, v0.y); }
        else        { fadd2(cs, v1.x); fadd2(cs, v1.y); }
        #pragma unroll
        for (int m = 0; m < 4; m++) {
            ffma2(acc[m][0], ra[m*22 + 2*h],     v0.x);
            ffma2(acc[m][0], ra[m*22 + 2*h + 1], v0.y);
            ffma2(acc[m][1], ra[m*22 + 2*h],     v1.x);
            ffma2(acc[m][1], ra[m*22 + 2*h + 1], v1.y);
        }
    }
    // smem half: e pairs 22..31 (ulonglong2 11..15)
    const ulonglong2* Asv = reinterpret_cast<const ulonglong2*>(As2);
    #pragma unroll
    for (int h = 0; h < 5; h++) {
        ulonglong2 v0 = e0[11 + h], v1 = e1[11 + h];
        if (p == 0) { fadd2(cs, v0.x); fadd2(cs, v0.y); }
        else        { fadd2(cs, v1.x); fadd2(cs, v1.y); }
        #pragma unroll
        for (int m = 0; m < 4; m++) {
            ulonglong2 av = Asv[(m*5 + h)*NT + tid];
            ffma2(acc[m][0], av.x, v0.x);
            ffma2(acc[m][0], av.y, v0.y);
            ffma2(acc[m][1], av.x, v1.x);
            ffma2(acc[m][1], av.y, v1.y);
        }
    }
    #pragma unroll
    for (int m = 0; m < 4; m++) {
        int j = 128*p + 32*m + l;
        part[q*256 + j] = packf2(psum1(acc[m][0]), psum1(acc[m][1]));
    }
    if (l == 0) ssum[p*4 + q] = psum1(cs);
}

// ---------------- main persistent kernel ----------------
__global__ void __launch_bounds__(NT, 1)
hmm_fb(const int* __restrict__ obs, float* __restrict__ out) {
    extern __shared__ float sm[];
    ull*   As2   = (ull*)sm;                    // 40*NT u64 = 80KB
    ull*   part  = As2 + 40*NT;                 // [4q][256] packed u64 = 8KB
    float* es    = (float*)(part + 4*256);      // [2][Kk]
    float* ssum  = es + 2*Kk;                   // [2seq][4q]
    int*   obs_s = (int*)(ssum + 8);            // [2][Tt]

    const int tid = threadIdx.x, wi = tid >> 5, l = tid & 31;
    const int p = wi >> 2, q = wi & 3;
    const int n0 = 2*blockIdx.x, n1 = n0 + 1;

    for (int i = tid; i < Tt; i += NT) {
        obs_s[i]      = obs[n0*Tt + i];
        obs_s[Tt + i] = obs[n1*Tt + i];
    }

    ull ra[88];
    #pragma unroll
    for (int k = 0; k < 88; k++) ra[k] = g_Freg[k*NT + tid];
    {
        const ulonglong2* src = reinterpret_cast<const ulonglong2*>(g_Fsm);
        ulonglong2*       dst = reinterpret_cast<ulonglong2*>(As2);
        #pragma unroll
        for (int k = 0; k < 20; k++) dst[k*NT + tid] = src[k*NT + tid];
    }

    float* out0 = out + (size_t)n0*Tt*Kk + tid;
    float* out1 = out + (size_t)n1*Tt*Kk + tid;

    float w0, w1;

    // ---- forward init (t = 0) ----
    {
        float pi = g_pi[tid];
        w0 = pi * g_Bt[obs_s[0]  * Kk + tid];
        w1 = pi * g_Bt[obs_s[Tt] * Kk + tid];
        es[tid] = w0; es[Kk + tid] = w1;
        __syncthreads();    // es + A-cache published
    }

    // ---- forward loop ----
    for (int t = 1; t < Tt; t++) {
        float bb0 = g_Bt[obs_s[t]      * Kk + tid];
        float bb1 = g_Bt[obs_s[Tt + t] * Kk + tid];
        do_dot(ra, As2, es, part, ssum, p, q, l, tid);
        __syncthreads();                                   // part + ssum ready
        float4 cv0 = *reinterpret_cast<const float4*>(ssum);
        float4 cv1 = *reinterpret_cast<const float4*>(ssum + 4);
        ull us = 0;
        #pragma unroll
        for (int k = 0; k < 4; k++) fadd2(us, part[k*256 + tid]);
        float s0, s1; unpackf2(us, s0, s1);
        float r0 = __fdividef(1.f, (cv0.x + cv0.y) + (cv0.z + cv0.w));
        float r1 = __fdividef(1.f, (cv1.x + cv1.y) + (cv1.z + cv1.w));
        out0[(size_t)(t-1)*Kk] = w0 * r0;                  // scale need not be exact
        out1[(size_t)(t-1)*Kk] = w1 * r1;
        w0 = s0 * r0 * bb0;
        w1 = s1 * r1 * bb1;
        es[tid] = w0; es[Kk + tid] = w1;
        __syncthreads();                                   // es ready for next dot
    }
    // last row: any per-row scale works (epilogue renormalizes)
    out0[(size_t)(Tt-1)*Kk] = w0;
    out1[(size_t)(Tt-1)*Kk] = w1;
    __syncthreads();

    // ---- reload A-pack for backward ----
    #pragma unroll
    for (int k = 0; k < 88; k++) ra[k] = g_Breg[k*NT + tid];
    {
        const ulonglong2* src = reinterpret_cast<const ulonglong2*>(g_Bsm);
        ulonglong2*       dst = reinterpret_cast<ulonglong2*>(As2);
        #pragma unroll
        for (int k = 0; k < 20; k++) dst[k*NT + tid] = src[k*NT + tid];
    }

    // ---- backward init: y_{T-1} = B[:,o_{T-1}] (beta = 1) ----
    {
        float y0 = g_Bt[obs_s[Tt-1]      * Kk + tid];
        float y1 = g_Bt[obs_s[Tt + Tt-1] * Kk + tid];
        es[tid] = y0; es[Kk + tid] = y1;
        __syncthreads();
    }

    // ---- backward loop ----
    for (int t = Tt - 2; t >= 0; t--) {
        float pp0 = out0[(size_t)t*Kk];                    // prefetch p_t
        float pp1 = out1[(size_t)t*Kk];
        float bb0 = g_Bt[obs_s[t]      * Kk + tid];
        float bb1 = g_Bt[obs_s[Tt + t] * Kk + tid];
        do_dot(ra, As2, es, part, ssum, p, q, l, tid);
        __syncthreads();
        float4 cv0 = *reinterpret_cast<const float4*>(ssum);
        float4 cv1 = *reinterpret_cast<const float4*>(ssum + 4);
        ull us = 0;
        #pragma unroll
        for (int k = 0; k < 4; k++) fadd2(us, part[k*256 + tid]);
        float s0, s1; unpackf2(us, s0, s1);
        float r0 = __fdividef(1.f, (cv0.x + cv0.y) + (cv0.z + cv0.w));
        float r1 = __fdividef(1.f, (cv1.x + cv1.y) + (cv1.z + cv1.w));
        float be0 = s0 * r0, be1 = s1 * r1;                // scaled beta_t
        out0[(size_t)t*Kk] = pp0 * be0;                    // unnormalized gamma
        out1[(size_t)t*Kk] = pp1 * be1;
        float y0 = be0 * bb0, y1 = be1 * bb1;
        es[tid] = y0; es[Kk + tid] = y1;
        __syncthreads();
    }
}

// ---------------- epilogue: per-(n,t) log-normalize ----------------
__global__ void __launch_bounds__(256)
norm_gamma(float* __restrict__ out) {
    int row  = (blockIdx.x << 3) + (threadIdx.x >> 5);
    int lane = threadIdx.x & 31;
    float4* p = reinterpret_cast<float4*>(out + (size_t)row * Kk);
    float4 v0 = p[lane], v1 = p[lane + 32];
    float s = v0.x + v0.y + v0.z + v0.w + v1.x + v1.y + v1.z + v1.w;
    #pragma unroll
    for (int o = 16; o; o >>= 1) s += __shfl_xor_sync(0xFFFFFFFFu, s, o);
    float lc = __logf(s);
    v0.x = __logf(v0.x) - lc; v0.y = __logf(v0.y) - lc;
    v0.z = __logf(v0.z) - lc; v0.w = __logf(v0.w) - lc;
    v1.x = __logf(v1.x) - lc; v1.y = __logf(v1.y) - lc;
    v1.z = __logf(v1.z) - lc; v1.w = __logf(v1.w) - lc;
    p[lane] = v0; p[lane + 32] = v1;
}

// ---------------- launch ----------------
extern "C" void kernel_launch(void* const* d_in, const int* in_sizes, int n_in,
                              void* d_out, int out_size) {
    const float* log_pi = (const float*)d_in[0];
    const float* log_A  = (const float*)d_in[1];
    const float* log_B  = (const float*)d_in[2];
    const int*   observ = (const int*)  d_in[3];
    float* out = (float*)d_out;

    const int smem_bytes = 40*NT*8 + 4*256*8 + (2*Kk + 8)*4 + 2*Tt*4;
    cudaFuncSetAttribute(hmm_fb, cudaFuncAttributeMaxDynamicSharedMemorySize, smem_bytes);

    prep_pack<<<128, 256>>>(log_A, log_pi);
    prep_B<<<(Kk*Vv + 255)/256, 256>>>(log_B);
    hmm_fb<<<NC, NT, smem_bytes>>>(observ, out);
    norm_gamma<<<(NBb*Tt)/8, 256>>>(out);
}

// round 15
// speedup vs baseline: 1.0192x; 1.0192x over previous
#include <cuda_runtime.h>
#include <math.h>
#include <stdint.h>

#define Kk 256
#define Tt 512
#define NBb 256
#define Vv 4096

#define NT 256
#define NC (NBb/2)      // 128 CTAs, 2 sequences each

// Warp tiling: 8 warps = 2 (p) x 4 (q). Warp (p,q): output states
// {128p+32m+lane, m=0..3}, summation i in [64q,64q+64).
// Per thread: 4 states x 64 i = 128 u64 pairs; 72 in regs (c=0..17 per
// state), 56 via smem (c=18..31). Two barriers per step (champion R7
// structure), slice-sum accumulated inside the dot. Partials for both
// sequences exchanged as ONE packed u64 per (q, state).

typedef unsigned long long ull;

// ---------------- device scratch ----------------
__device__ ull  g_Freg[72*NT];     // forward  A-pack, register part
__device__ ull  g_Fsm [56*NT];     // forward  A-pack, smem part
__device__ ull  g_Breg[72*NT];     // backward A-pack, register part
__device__ ull  g_Bsm [56*NT];     // backward A-pack, smem part
__device__ float g_Bt[Vv*Kk];      // exp(log_B) transposed: [v][j]
__device__ float g_pi[Kk];

// ---------------- prep ----------------
__global__ void prep_pack(const float* __restrict__ logA, const float* __restrict__ logpi) {
    int idx = blockIdx.x * blockDim.x + threadIdx.x;   // 0 .. 32767
    if (idx < Kk) g_pi[idx] = expf(logpi[idx]);
    int tid = idx & 255;
    int k   = idx >> 8;            // 0..127 : k = m*32 + c
    int m = k >> 5, c = k & 31;
    int wi = tid >> 5, l = tid & 31;
    int p = wi >> 2, q = wi & 3;
    int j = 128*p + 32*m + l;      // output state
    int i = 64*q + 2*c;            // summation index (pair base)
    float f0 = expf(logA[i*Kk + j]);        // fwd: sum_i e[i]*A[i][j]
    float f1 = expf(logA[(i+1)*Kk + j]);
    float b0 = expf(logA[j*Kk + i]);        // bwd: sum_i e[i]*A[j][i]
    float b1 = expf(logA[j*Kk + i + 1]);
    ull fv = ((ull)__float_as_uint(f1) << 32) | __float_as_uint(f0);
    ull bv = ((ull)__float_as_uint(b1) << 32) | __float_as_uint(b0);
    if (c < 18) {
        g_Freg[(m*18 + c)*NT + tid] = fv;
        g_Breg[(m*18 + c)*NT + tid] = bv;
    } else {
        int cc = c - 18;
        int u = (((m*7 + (cc>>1))*NT + tid) << 1) | (cc & 1);  // ulonglong2-friendly
        g_Fsm[u] = fv;
        g_Bsm[u] = bv;
    }
}

__global__ void prep_B(const float* __restrict__ logB) {
    int idx = blockIdx.x * blockDim.x + threadIdx.x;   // j*Vv + v (coalesced read)
    if (idx >= Kk*Vv) return;
    int j = idx / Vv, v = idx % Vv;
    g_Bt[v*Kk + j] = expf(logB[idx]);
}

// ---------------- helpers ----------------
__device__ __forceinline__ void ffma2(ull& d, ull a, ull b) {
    asm("fma.rn.f32x2 %0, %1, %2, %0;" : "+l"(d) : "l"(a), "l"(b));
}
__device__ __forceinline__ void fadd2(ull& d, ull a) {
    asm("add.rn.f32x2 %0, %0, %1;" : "+l"(d) : "l"(a));
}
__device__ __forceinline__ float psum1(ull a) {
    unsigned lo, hi; asm("mov.b64 {%0,%1}, %2;" : "=r"(lo), "=r"(hi) : "l"(a));
    return __uint_as_float(lo) + __uint_as_float(hi);
}
__device__ __forceinline__ ull packf2(float lo, float hi) {
    ull r; asm("mov.b64 %0, {%1,%2};" : "=l"(r) : "r"(__float_as_uint(lo)), "r"(__float_as_uint(hi)));
    return r;
}
__device__ __forceinline__ void unpackf2(ull a, float& lo, float& hi) {
    unsigned ulo, uhi; asm("mov.b64 {%0,%1}, %2;" : "=r"(ulo), "=r"(uhi) : "l"(a));
    lo = __uint_as_float(ulo); hi = __uint_as_float(uhi);
}

// split-K dot: this warp covers i in [64q,64q+64) for its 4 states, both seqs.
// Warp (p,q) also accumulates the slice-sum of seq p's e-slice -> ssum[p*4+q].
// Partials for both seqs are packed into one u64 per (q, state).
__device__ __forceinline__ void do_dot(const ull (&ra)[72],
                                       const ull* __restrict__ As2,
                                       const float* __restrict__ es,   // [2][Kk]
                                       ull* __restrict__ part,         // [4q][256j] packed
                                       float* __restrict__ ssum,       // [2][4]
                                       int p, int q, int l, int tid) {
    const ulonglong2* e0 = reinterpret_cast<const ulonglong2*>(es + 64*q);
    const ulonglong2* e1 = reinterpret_cast<const ulonglong2*>(es + Kk + 64*q);
    ull acc[4][2] = {};
    ull cs = 0;
    // register half: e pairs 0..17 (ulonglong2 0..8)
    #pragma unroll
    for (int h = 0; h < 9; h++) {
        ulonglong2 v0 = e0[h], v1 = e1[h];
        if (p == 0) { fadd2(cs, v0.x); fadd2(cs, v0.y); }
        else        { fadd2(cs, v1.x); fadd2(cs, v1.y); }
        #pragma unroll
        for (int m = 0; m < 4; m++) {
            ffma2(acc[m][0], ra[m*18 + 2*h],     v0.x);
            ffma2(acc[m][0], ra[m*18 + 2*h + 1], v0.y);
            ffma2(acc[m][1], ra[m*18 + 2*h],     v1.x);
            ffma2(acc[m][1], ra[m*18 + 2*h + 1], v1.y);
        }
    }
    // smem half: e pairs 18..31 (ulonglong2 9..15)
    const ulonglong2* Asv = reinterpret_cast<const ulonglong2*>(As2);
    #pragma unroll
    for (int h = 0; h < 7; h++) {
        ulonglong2 v0 = e0[9 + h], v1 = e1[9 + h];
        if (p == 0) { fadd2(cs, v0.x); fadd2(cs, v0.y); }
        else        { fadd2(cs, v1.x); fadd2(cs, v1.y); }
        #pragma unroll
        for (int m = 0; m < 4; m++) {
            ulonglong2 av = Asv[(m*7 + h)*NT + tid];
            ffma2(acc[m][0], av.x, v0.x);
            ffma2(acc[m][0], av.y, v0.y);
            ffma2(acc[m][1], av.x, v1.x);
            ffma2(acc[m][1], av.y, v1.y);
        }
    }
    #pragma unroll
    for (int m = 0; m < 4; m++) {
        int j = 128*p + 32*m + l;
        part[q*256 + j] = packf2(psum1(acc[m][0]), psum1(acc[m][1]));
    }
    if (l == 0) ssum[p*4 + q] = psum1(cs);
}

// ---------------- main persistent kernel ----------------
__global__ void __launch_bounds__(NT, 1)
hmm_fb(const int* __restrict__ obs, float* __restrict__ out) {
    extern __shared__ float sm[];
    ull*   As2   = (ull*)sm;                    // 56*NT u64 = 112KB
    ull*   part  = As2 + 56*NT;                 // [4q][256] packed u64 = 8KB
    float* es    = (float*)(part + 4*256);      // [2][Kk]
    float* ssum  = es + 2*Kk;                   // [2seq][4q]
    int*   obs_s = (int*)(ssum + 8);            // [2][Tt]

    const int tid = threadIdx.x, wi = tid >> 5, l = tid & 31;
    const int p = wi >> 2, q = wi & 3;
    const int n0 = 2*blockIdx.x, n1 = n0 + 1;

    for (int i = tid; i < Tt; i += NT) {
        obs_s[i]      = obs[n0*Tt + i];
        obs_s[Tt + i] = obs[n1*Tt + i];
    }

    ull ra[72];
    #pragma unroll
    for (int k = 0; k < 72; k++) ra[k] = g_Freg[k*NT + tid];
    {
        const ulonglong2* src = reinterpret_cast<const ulonglong2*>(g_Fsm);
        ulonglong2*       dst = reinterpret_cast<ulonglong2*>(As2);
        #pragma unroll
        for (int k = 0; k < 28; k++) dst[k*NT + tid] = src[k*NT + tid];
    }

    float* out0 = out + (size_t)n0*Tt*Kk + tid;
    float* out1 = out + (size_t)n1*Tt*Kk + tid;

    float w0, w1;

    // ---- forward init (t = 0) ----
    {
        float pi = g_pi[tid];
        w0 = pi * g_Bt[obs_s[0]  * Kk + tid];
        w1 = pi * g_Bt[obs_s[Tt] * Kk + tid];
        es[tid] = w0; es[Kk + tid] = w1;
        __syncthreads();    // es + A-cache published
    }

    // ---- forward loop ----
    for (int t = 1; t < Tt; t++) {
        float bb0 = g_Bt[obs_s[t]      * Kk + tid];
        float bb1 = g_Bt[obs_s[Tt + t] * Kk + tid];
        do_dot(ra, As2, es, part, ssum, p, q, l, tid);
        __syncthreads();                                   // part + ssum ready
        float4 cv0 = *reinterpret_cast<const float4*>(ssum);
        float4 cv1 = *reinterpret_cast<const float4*>(ssum + 4);
        ull us = 0;
        #pragma unroll
        for (int k = 0; k < 4; k++) fadd2(us, part[k*256 + tid]);
        float s0, s1; unpackf2(us, s0, s1);
        float r0 = __fdividef(1.f, (cv0.x + cv0.y) + (cv0.z + cv0.w));
        float r1 = __fdividef(1.f, (cv1.x + cv1.y) + (cv1.z + cv1.w));
        out0[(size_t)(t-1)*Kk] = w0 * r0;                  // scale need not be exact
        out1[(size_t)(t-1)*Kk] = w1 * r1;
        w0 = s0 * r0 * bb0;
        w1 = s1 * r1 * bb1;
        es[tid] = w0; es[Kk + tid] = w1;
        __syncthreads();                                   // es ready for next dot
    }
    // last row: any per-row scale works (epilogue renormalizes)
    out0[(size_t)(Tt-1)*Kk] = w0;
    out1[(size_t)(Tt-1)*Kk] = w1;
    __syncthreads();

    // ---- reload A-pack for backward ----
    #pragma unroll
    for (int k = 0; k < 72; k++) ra[k] = g_Breg[k*NT + tid];
    {
        const ulonglong2* src = reinterpret_cast<const ulonglong2*>(g_Bsm);
        ulonglong2*       dst = reinterpret_cast<ulonglong2*>(As2);
        #pragma unroll
        for (int k = 0; k < 28; k++) dst[k*NT + tid] = src[k*NT + tid];
    }

    // ---- backward init: y_{T-1} = B[:,o_{T-1}] (beta = 1) ----
    {
        float y0 = g_Bt[obs_s[Tt-1]      * Kk + tid];
        float y1 = g_Bt[obs_s[Tt + Tt-1] * Kk + tid];
        es[tid] = y0; es[Kk + tid] = y1;
        __syncthreads();
    }

    // ---- backward loop ----
    for (int t = Tt - 2; t >= 0; t--) {
        float pp0 = out0[(size_t)t*Kk];                    // prefetch p_t
        float pp1 = out1[(size_t)t*Kk];
        float bb0 = g_Bt[obs_s[t]      * Kk + tid];
        float bb1 = g_Bt[obs_s[Tt + t] * Kk + tid];
        do_dot(ra, As2, es, part, ssum, p, q, l, tid);
        __syncthreads();
        float4 cv0 = *reinterpret_cast<const float4*>(ssum);
        float4 cv1 = *reinterpret_cast<const float4*>(ssum + 4);
        ull us = 0;
        #pragma unroll
        for (int k = 0; k < 4; k++) fadd2(us, part[k*256 + tid]);
        float s0, s1; unpackf2(us, s0, s1);
        float r0 = __fdividef(1.f, (cv0.x + cv0.y) + (cv0.z + cv0.w));
        float r1 = __fdividef(1.f, (cv1.x + cv1.y) + (cv1.z + cv1.w));
        float be0 = s0 * r0, be1 = s1 * r1;                // scaled beta_t
        out0[(size_t)t*Kk] = pp0 * be0;                    // unnormalized gamma
        out1[(size_t)t*Kk] = pp1 * be1;
        float y0 = be0 * bb0, y1 = be1 * bb1;
        es[tid] = y0; es[Kk + tid] = y1;
        __syncthreads();
    }
}

// ---------------- epilogue: per-(n,t) log-normalize ----------------
__global__ void __launch_bounds__(256)
norm_gamma(float* __restrict__ out) {
    int row  = (blockIdx.x << 3) + (threadIdx.x >> 5);
    int lane = threadIdx.x & 31;
    float4* p = reinterpret_cast<float4*>(out + (size_t)row * Kk);
    float4 v0 = p[lane], v1 = p[lane + 32];
    float s = v0.x + v0.y + v0.z + v0.w + v1.x + v1.y + v1.z + v1.w;
    #pragma unroll
    for (int o = 16; o; o >>= 1) s += __shfl_xor_sync(0xFFFFFFFFu, s, o);
    float lc = __logf(s);
    v0.x = __logf(v0.x) - lc; v0.y = __logf(v0.y) - lc;
    v0.z = __logf(v0.z) - lc; v0.w = __logf(v0.w) - lc;
    v1.x = __logf(v1.x) - lc; v1.y = __logf(v1.y) - lc;
    v1.z = __logf(v1.z) - lc; v1.w = __logf(v1.w) - lc;
    p[lane] = v0; p[lane + 32] = v1;
}

// ---------------- launch ----------------
extern "C" void kernel_launch(void* const* d_in, const int* in_sizes, int n_in,
                              void* d_out, int out_size) {
    const float* log_pi = (const float*)d_in[0];
    const float* log_A  = (const float*)d_in[1];
    const float* log_B  = (const float*)d_in[2];
    const int*   observ = (const int*)  d_in[3];
    float* out = (float*)d_out;

    const int smem_bytes = 56*NT*8 + 4*256*8 + (2*Kk + 8)*4 + 2*Tt*4;
    cudaFuncSetAttribute(hmm_fb, cudaFuncAttributeMaxDynamicSharedMemorySize, smem_bytes);

    prep_pack<<<128, 256>>>(log_A, log_pi);
    prep_B<<<(Kk*Vv + 255)/256, 256>>>(log_B);
    hmm_fb<<<NC, NT, smem_bytes>>>(observ, out);
    norm_gamma<<<(NBb*Tt)/8, 256>>>(out);
}